// round 6
// baseline (speedup 1.0000x reference)
#include <cuda_runtime.h>
#include <math.h>

#define Bb 8
#define NPTS 20000
#define PP 256
#define SS 32
#define CC 256
#define NCLS 18

// ---- output layout (concatenated float32) ----
#define OFF_NF   6144
#define OFF_LAB  268288
#define OFF_INDS 792576

// ---- scratch ----
__device__ float d_featT[(size_t)Bb*NPTS*CC];   // [B][N][C]
__device__ float d_x[Bb*NPTS], d_y[Bb*NPTS], d_z[Bb*NPTS];
__device__ int   d_samp[Bb*PP*SS];
__device__ float d_center[Bb*PP*3];
__device__ float d_nf[Bb*PP*128];
__device__ float d_ss256[Bb*256];
__device__ float d_ss512[Bb*512];
// vectorized weights: [(c4*O+o)*4+j] = W[o][c4*4+j] (0-pad)
__device__ float d_w0v[65*128*4];
__device__ float d_w1v[32*128*4];
__device__ float d_w2v[32*128*4];
__device__ float d_l0v[37*256*4];
__device__ float d_l1v[64*256*4];
__device__ float d_l2v[64*256*4];
// transposed time-MLP weights: Wt[i*O+o] = W[o*I+i]
__device__ float d_tw0T[128*512];
__device__ float d_tw1T[512*512];
__device__ float d_bwT[512*256];
__device__ float d_tlw0T[256*1024];
__device__ float d_tlw1T[1024*1024];
__device__ float d_blwT[1024*512];

// ---- packed f32x2 helpers ----
__device__ __forceinline__ unsigned long long pack2(float x, float y) {
    unsigned long long r;
    asm("mov.b64 %0, {%1, %2};" : "=l"(r) : "f"(x), "f"(y));
    return r;
}
__device__ __forceinline__ void unpack2(unsigned long long v, float& x, float& y) {
    asm("mov.b64 {%0, %1}, %2;" : "=f"(x), "=f"(y) : "l"(v));
}
__device__ __forceinline__ void ffma2(unsigned long long& d, unsigned long long a,
                                      unsigned long long b) {
    asm("fma.rn.f32x2 %0, %1, %2, %0;" : "+l"(d) : "l"(a), "l"(b));
}

__device__ __forceinline__ float gelu_exact(float x) {
    return 0.5f * x * (1.0f + erff(x * 0.70710678118654752f));
}
__device__ __forceinline__ float silu_f(float x) {
    return x / (1.0f + expf(-x));
}

// ======================= k_pre: xyz SoA split + time-weight transposes ======
#define XYZ_BLKS ((Bb*NPTS + 255) / 256)          // 625
#define PREP2_TOTAL (128*512 + 512*512 + 512*256 + 256*1024 + 1024*1024 + 1024*512)
#define PREP2_BLKS (PREP2_TOTAL / 256)            // 9216
__device__ __forceinline__ void tr_one(float* dst, const float* src,
                                       int I, int O, int idx) {
    int o = idx % O, i = idx / O;
    dst[idx] = src[o * I + i];
}
__global__ void __launch_bounds__(256)
k_pre(const float* __restrict__ xyz,
      const float* __restrict__ tw0, const float* __restrict__ tw1,
      const float* __restrict__ bw, const float* __restrict__ tlw0,
      const float* __restrict__ tlw1, const float* __restrict__ blw) {
    int blk = blockIdx.x;
    if (blk < XYZ_BLKS) {
        int i = blk * 256 + threadIdx.x;
        if (i < Bb * NPTS) {
            d_x[i] = xyz[i * 3 + 0];
            d_y[i] = xyz[i * 3 + 1];
            d_z[i] = xyz[i * 3 + 2];
        }
        return;
    }
    int i = (blk - XYZ_BLKS) * 256 + threadIdx.x;
    int off = 0;
    if (i < off + 128*512)   { tr_one(d_tw0T,  tw0,  128,  512,  i - off); return; } off += 128*512;
    if (i < off + 512*512)   { tr_one(d_tw1T,  tw1,  512,  512,  i - off); return; } off += 512*512;
    if (i < off + 512*256)   { tr_one(d_bwT,   bw,   512,  256,  i - off); return; } off += 512*256;
    if (i < off + 256*1024)  { tr_one(d_tlw0T, tlw0, 256,  1024, i - off); return; } off += 256*1024;
    if (i < off + 1024*1024) { tr_one(d_tlw1T, tlw1, 1024, 1024, i - off); return; } off += 1024*1024;
    if (i < off + 1024*512)  { tr_one(d_blwT,  blw,  1024, 512,  i - off); return; }
}

// ======================= k_front: select + featT + prep1 + time ============
#define SEL_BLKS (Bb * PP)                         // 2048
#define FT_BLKS  ((NPTS / 32) * (CC / 32) * Bb)    // 40000
#define S_W0 (65*128*4)
#define S_W1 (32*128*4)
#define S_L0 (37*256*4)
#define S_L1 (64*256*4)
#define PREP1_TOTAL (S_W0 + 2*S_W1 + S_L0 + 2*S_L1)
#define PREP1_BLKS ((PREP1_TOTAL + 255) / 256)     // 918
#define TIME_BLKS 16
#define FRONT_BLKS (SEL_BLKS + FT_BLKS + PREP1_BLKS + TIME_BLKS)

__device__ __forceinline__ void vec_one(float* dst, const float* W,
                                        int O, int Cin, int i) {
    int j = i & 3, r = i >> 2;
    int o = r % O, c4 = r / O, c = c4 * 4 + j;
    dst[i] = (c < Cin) ? W[o * Cin + c] : 0.f;
}

__device__ void do_select(int bp, int t, const float* __restrict__ bsize,
                          const int* __restrict__ inds, float* __restrict__ out) {
    __shared__ float tile_or_sel[32 * 33];   // reuse union-ish: select uses little
    (void)tile_or_sel;
    __shared__ int wcnt[8];
    __shared__ int sbuf[SS];
    __shared__ int sbase;
    int b = bp >> 8;
    int lane = t & 31, wid = t >> 5;
    int ind = inds[bp];
    const float* xb = d_x + b * NPTS;
    const float* yb = d_y + b * NPTS;
    const float* zb = d_z + b * NPTS;
    float cx = xb[ind], cy = yb[ind], cz = zb[ind];
    float hx = bsize[bp * 3 + 0] * 0.5f;
    float hy = bsize[bp * 3 + 1] * 0.5f;
    float hz = bsize[bp * 3 + 2] * 0.5f;
    if (t == 0) sbase = 0;
    __syncthreads();
    for (int base = 0; base < NPTS; base += 256) {
        int i = base + t;
        bool in = false;
        if (i < NPTS)
            in = (fabsf(xb[i] - cx) <= hx) && (fabsf(yb[i] - cy) <= hy) &&
                 (fabsf(zb[i] - cz) <= hz);
        unsigned m = __ballot_sync(0xffffffffu, in);
        if (lane == 0) wcnt[wid] = __popc(m);
        __syncthreads();
        int pre = sbase;
        #pragma unroll
        for (int w = 0; w < 8; w++) pre += (w < wid) ? wcnt[w] : 0;
        if (in) {
            int r = pre + __popc(m & ((1u << lane) - 1u));
            if (r < SS) sbuf[r] = i;
        }
        __syncthreads();
        if (t == 0) {
            int tot = 0;
            #pragma unroll
            for (int w = 0; w < 8; w++) tot += wcnt[w];
            sbase += tot;
        }
        __syncthreads();
        if (sbase >= SS) break;
    }
    int ce = sbase < SS ? sbase : SS;   // >= 1 (center point inside its own box)
    if (t < SS) d_samp[bp * SS + t] = sbuf[t % ce];
    if (t < 3) {
        float cv = (t == 0) ? cx : ((t == 1) ? cy : cz);
        out[bp * 3 + t] = cv;
        d_center[bp * 3 + t] = cv;
    }
    if (t == 0) out[OFF_INDS + bp] = (float)ind;
}

__device__ void do_featT(int f, int t, const float* __restrict__ feat) {
    __shared__ float tile[32 * 33];
    int n0 = (f % 625) * 32;
    int rest = f / 625;
    int c0 = (rest & 7) * 32;
    int b = rest >> 3;
    int tx = t & 31, ty = t >> 5;   // 32 x 8
    const float* src = feat + ((size_t)b * CC + c0) * NPTS + n0;
    #pragma unroll
    for (int j = 0; j < 32; j += 8) tile[(ty + j) * 33 + tx] = src[(size_t)(ty + j) * NPTS + tx];
    __syncthreads();
    float* dst = d_featT + ((size_t)b * NPTS + n0) * CC + c0;
    #pragma unroll
    for (int j = 0; j < 32; j += 8) dst[(size_t)(ty + j) * CC + tx] = tile[tx * 33 + ty + j];
}

__device__ void do_time(int blk, int t, const float* __restrict__ ts,
                        const float* __restrict__ tb0, const float* __restrict__ tb1,
                        const float* __restrict__ bb,
                        const float* __restrict__ tlb0, const float* __restrict__ tlb1,
                        const float* __restrict__ blb) {
    __shared__ float e[256];
    __shared__ float h1[1024];
    __shared__ float h2[1024];
    int chain = blk >> 3;
    int b = blk & 7;
    float tsv = ts[b];
    if (chain == 0) {
        if (t < 128) {
            int k = (t < 64) ? t : t - 64;
            float fr = expf((float)k * (float)(-9.210340371976184 / 63.0));
            float ev = tsv * fr;
            e[t] = (float)((t < 64) ? sin((double)ev) : cos((double)ev));
        }
        __syncthreads();
        #pragma unroll
        for (int k = 0; k < 2; k++) {
            int o = t + k * 256;
            float acc = tb0[o];
            #pragma unroll 4
            for (int i = 0; i < 128; i++) acc = fmaf(e[i], d_tw0T[i * 512 + o], acc);
            h1[o] = gelu_exact(acc);
        }
        __syncthreads();
        #pragma unroll
        for (int k = 0; k < 2; k++) {
            int o = t + k * 256;
            float acc = tb1[o];
            #pragma unroll 4
            for (int i = 0; i < 512; i++) acc = fmaf(h1[i], d_tw1T[i * 512 + o], acc);
            h2[o] = silu_f(acc);
        }
        __syncthreads();
        {
            float acc = bb[t];
            #pragma unroll 4
            for (int i = 0; i < 512; i++) acc = fmaf(h2[i], d_bwT[i * 256 + t], acc);
            d_ss256[b * 256 + t] = acc;
        }
    } else {
        if (t < 256) {
            int k = (t < 128) ? t : t - 128;
            float fr = expf((float)k * (float)(-9.210340371976184 / 127.0));
            float ev = tsv * fr;
            e[t] = (float)((t < 128) ? sin((double)ev) : cos((double)ev));
        }
        __syncthreads();
        #pragma unroll
        for (int k = 0; k < 4; k++) {
            int o = t + k * 256;
            float acc = tlb0[o];
            #pragma unroll 4
            for (int i = 0; i < 256; i++) acc = fmaf(e[i], d_tlw0T[i * 1024 + o], acc);
            h1[o] = gelu_exact(acc);
        }
        __syncthreads();
        #pragma unroll
        for (int k = 0; k < 4; k++) {
            int o = t + k * 256;
            float acc = tlb1[o];
            #pragma unroll 4
            for (int i = 0; i < 1024; i++) acc = fmaf(h1[i], d_tlw1T[i * 1024 + o], acc);
            h2[o] = silu_f(acc);
        }
        __syncthreads();
        #pragma unroll
        for (int k = 0; k < 2; k++) {
            int o = t + k * 256;
            float acc = blb[o];
            #pragma unroll 4
            for (int i = 0; i < 1024; i++) acc = fmaf(h2[i], d_blwT[i * 512 + o], acc);
            d_ss512[b * 512 + o] = acc;
        }
    }
}

__global__ void __launch_bounds__(256)
k_front(const float* __restrict__ feat, const float* __restrict__ bsize,
        const int* __restrict__ inds, const float* __restrict__ ts,
        const float* __restrict__ mw0, const float* __restrict__ mw1,
        const float* __restrict__ mw2, const float* __restrict__ lw0,
        const float* __restrict__ lw1, const float* __restrict__ lw2,
        const float* __restrict__ tb0, const float* __restrict__ tb1,
        const float* __restrict__ bb,
        const float* __restrict__ tlb0, const float* __restrict__ tlb1,
        const float* __restrict__ blb,
        float* __restrict__ out) {
    int blk = blockIdx.x;
    int t = threadIdx.x;
    if (blk < SEL_BLKS) { do_select(blk, t, bsize, inds, out); return; }
    blk -= SEL_BLKS;
    if (blk < FT_BLKS) { do_featT(blk, t, feat); return; }
    blk -= FT_BLKS;
    if (blk < PREP1_BLKS) {
        int i = blk * 256 + t;
        int off = 0;
        if (i < off + S_W0) { vec_one(d_w0v, mw0, 128, 259, i - off); return; } off += S_W0;
        if (i < off + S_W1) { vec_one(d_w1v, mw1, 128, 128, i - off); return; } off += S_W1;
        if (i < off + S_W1) { vec_one(d_w2v, mw2, 128, 128, i - off); return; } off += S_W1;
        if (i < off + S_L0) { vec_one(d_l0v, lw0, 256, 146, i - off); return; } off += S_L0;
        if (i < off + S_L1) { vec_one(d_l1v, lw1, 256, 256, i - off); return; } off += S_L1;
        if (i < off + S_L1) { vec_one(d_l2v, lw2, 256, 256, i - off); return; }
        return;
    }
    blk -= PREP1_BLKS;
    do_time(blk, t, ts, tb0, tb1, bb, tlb0, tlb1, blb);
}

// ======================= point MLP (packed f32x2) ==========================
#define GROWS 260
#define RS 18            // row stride in float2 (even -> 16B-aligned LDS.128)
__global__ void __launch_bounds__(128)
k_pointmlp(const float* __restrict__ xyz,
           const float* __restrict__ mb0, const float* __restrict__ mb1,
           const float* __restrict__ mb2) {
    int bp = blockIdx.x;
    int b = bp >> 8;
    int t = threadIdx.x;
    __shared__ __align__(16) float2 g2[GROWS * RS];
    __shared__ int sidx[SS];
    __shared__ float ctr[3];
    float* gf = (float*)g2;
    if (t < SS) sidx[t] = d_samp[bp * SS + t];
    if (t < 3)  ctr[t] = d_center[bp * 3 + t];
    __syncthreads();
    if (t < 96) {
        int s = t / 3, d = t % 3;
        gf[d * (2 * RS) + s] = xyz[((size_t)b * NPTS + sidx[s]) * 3 + d] - ctr[d];
    }
    if (t < SS) gf[259 * (2 * RS) + t] = 0.f;
    {
        int s = t >> 2, q = t & 3;
        const float4* fr = (const float4*)(d_featT + ((size_t)b * NPTS + sidx[s]) * CC);
        #pragma unroll
        for (int k = 0; k < 16; k++) {
            float4 v = fr[q + 4 * k];
            int c = 4 * (q + 4 * k);
            gf[(3 + c) * (2 * RS) + s] = v.x;
            gf[(4 + c) * (2 * RS) + s] = v.y;
            gf[(5 + c) * (2 * RS) + s] = v.z;
            gf[(6 + c) * (2 * RS) + s] = v.w;
        }
    }
    __syncthreads();

    unsigned long long acc[16];
    {
        float bv = mb0[t];
        unsigned long long b2 = pack2(bv, bv);
        #pragma unroll
        for (int i = 0; i < 16; i++) acc[i] = b2;
        const float4* wv = (const float4*)d_w0v;
        for (int c4 = 0; c4 < 65; c4++) {
            float4 w = wv[c4 * 128 + t];
            #pragma unroll
            for (int cj = 0; cj < 4; cj++) {
                float wj = (cj == 0) ? w.x : (cj == 1) ? w.y : (cj == 2) ? w.z : w.w;
                unsigned long long wp = pack2(wj, wj);
                const ulonglong2* row = (const ulonglong2*)(g2 + (c4 * 4 + cj) * RS);
                #pragma unroll
                for (int s4 = 0; s4 < 8; s4++) {
                    ulonglong2 gg = row[s4];
                    ffma2(acc[2 * s4],     gg.x, wp);
                    ffma2(acc[2 * s4 + 1], gg.y, wp);
                }
            }
        }
    }
    __syncthreads();
    float2* h0 = g2;
    float2* h1 = g2 + 128 * RS;
    #pragma unroll
    for (int i = 0; i < 16; i++) {
        float lo, hi; unpack2(acc[i], lo, hi);
        h0[t * RS + i] = make_float2(fmaxf(lo, 0.f), fmaxf(hi, 0.f));
    }
    __syncthreads();
    for (int layer = 0; layer < 2; layer++) {
        const float4* wv = (const float4*)(layer == 0 ? d_w1v : d_w2v);
        float bv = (layer == 0) ? mb1[t] : mb2[t];
        const float2* hin = (layer == 0) ? h0 : h1;
        unsigned long long b2 = pack2(bv, bv);
        #pragma unroll
        for (int i = 0; i < 16; i++) acc[i] = b2;
        for (int c4 = 0; c4 < 32; c4++) {
            float4 w = wv[c4 * 128 + t];
            #pragma unroll
            for (int cj = 0; cj < 4; cj++) {
                float wj = (cj == 0) ? w.x : (cj == 1) ? w.y : (cj == 2) ? w.z : w.w;
                unsigned long long wp = pack2(wj, wj);
                const ulonglong2* row = (const ulonglong2*)(hin + (c4 * 4 + cj) * RS);
                #pragma unroll
                for (int s4 = 0; s4 < 8; s4++) {
                    ulonglong2 gg = row[s4];
                    ffma2(acc[2 * s4],     gg.x, wp);
                    ffma2(acc[2 * s4 + 1], gg.y, wp);
                }
            }
        }
        __syncthreads();
        if (layer == 0) {
            #pragma unroll
            for (int i = 0; i < 16; i++) {
                float lo, hi; unpack2(acc[i], lo, hi);
                h1[t * RS + i] = make_float2(fmaxf(lo, 0.f), fmaxf(hi, 0.f));
            }
            __syncthreads();
        } else {
            float mm = -1e30f;
            #pragma unroll
            for (int i = 0; i < 16; i++) {
                float lo, hi; unpack2(acc[i], lo, hi);
                mm = fmaxf(mm, fmaxf(lo, hi));
            }
            d_nf[bp * 128 + t] = fmaxf(mm, 0.f);
        }
    }
}

// ======================= label branch + FiLM epilogues =====================
__global__ void __launch_bounds__(256)
k_label(const float* __restrict__ blabel,
        const float* __restrict__ lb0, const float* __restrict__ lb1,
        const float* __restrict__ lb2, float* __restrict__ out) {
    int bp = blockIdx.x;
    int b = bp >> 8, p = bp & 255;
    int t = threadIdx.x;
    __shared__ __align__(16) float li[148];
    __shared__ __align__(16) float h[256];
    if (t < 148) {
        float v = 0.f;
        if (t < NCLS) v = blabel[bp * NCLS + t];
        else if (t < NCLS + 128) v = d_nf[bp * 128 + (t - NCLS)];
        li[t] = v;
    }
    if (t < 128) {
        float m = d_nf[bp * 128 + t];
        int pm = p & 127;
        float sc = d_ss256[b * 256 + pm] + 1.f;
        float sh = d_ss256[b * 256 + 128 + pm];
        out[OFF_NF + ((size_t)b * 128 + t) * 256 + p] = fmaf(m, sc, sh);
    }
    __syncthreads();
    float acc = lb0[t];
    {
        const float4* wv = (const float4*)d_l0v;
        for (int c4 = 0; c4 < 37; c4++) {
            float4 w = wv[c4 * 256 + t];
            float4 gv = *(const float4*)(li + c4 * 4);
            acc = fmaf(gv.x, w.x, acc); acc = fmaf(gv.y, w.y, acc);
            acc = fmaf(gv.z, w.z, acc); acc = fmaf(gv.w, w.w, acc);
        }
    }
    h[t] = fmaxf(acc, 0.f);
    __syncthreads();
    acc = lb1[t];
    {
        const float4* wv = (const float4*)d_l1v;
        for (int c4 = 0; c4 < 64; c4++) {
            float4 w = wv[c4 * 256 + t];
            float4 gv = *(const float4*)(h + c4 * 4);
            acc = fmaf(gv.x, w.x, acc); acc = fmaf(gv.y, w.y, acc);
            acc = fmaf(gv.z, w.z, acc); acc = fmaf(gv.w, w.w, acc);
        }
    }
    __syncthreads();
    h[t] = fmaxf(acc, 0.f);
    __syncthreads();
    acc = lb2[t];
    {
        const float4* wv = (const float4*)d_l2v;
        for (int c4 = 0; c4 < 64; c4++) {
            float4 w = wv[c4 * 256 + t];
            float4 gv = *(const float4*)(h + c4 * 4);
            acc = fmaf(gv.x, w.x, acc); acc = fmaf(gv.y, w.y, acc);
            acc = fmaf(gv.z, w.z, acc); acc = fmaf(gv.w, w.w, acc);
        }
    }
    float val = fmaxf(acc, 0.f);
    float sc = d_ss512[b * 512 + p] + 1.f;
    float sh = d_ss512[b * 512 + 256 + p];
    out[OFF_LAB + ((size_t)b * 256 + t) * 256 + p] = fmaf(val, sc, sh);
}

extern "C" void kernel_launch(void* const* d_in, const int* in_sizes, int n_in,
                              void* d_out, int out_size) {
    const float* xyz    = (const float*)d_in[0];
    const float* feats  = (const float*)d_in[1];
    const float* bsize  = (const float*)d_in[2];
    const float* blabel = (const float*)d_in[3];
    const float* ts     = (const float*)d_in[4];
    const int*   inds   = (const int*)d_in[5];
    const float* mw0 = (const float*)d_in[6];  const float* mb0 = (const float*)d_in[7];
    const float* mw1 = (const float*)d_in[8];  const float* mb1 = (const float*)d_in[9];
    const float* mw2 = (const float*)d_in[10]; const float* mb2 = (const float*)d_in[11];
    const float* lw0 = (const float*)d_in[12]; const float* lb0 = (const float*)d_in[13];
    const float* lw1 = (const float*)d_in[14]; const float* lb1 = (const float*)d_in[15];
    const float* lw2 = (const float*)d_in[16]; const float* lb2 = (const float*)d_in[17];
    const float* tw0 = (const float*)d_in[18]; const float* tb0 = (const float*)d_in[19];
    const float* tw1 = (const float*)d_in[20]; const float* tb1 = (const float*)d_in[21];
    const float* bw  = (const float*)d_in[22]; const float* bb  = (const float*)d_in[23];
    const float* tlw0 = (const float*)d_in[24]; const float* tlb0 = (const float*)d_in[25];
    const float* tlw1 = (const float*)d_in[26]; const float* tlb1 = (const float*)d_in[27];
    const float* blw  = (const float*)d_in[28]; const float* blb  = (const float*)d_in[29];
    float* out = (float*)d_out;

    k_pre<<<XYZ_BLKS + PREP2_BLKS, 256>>>(xyz, tw0, tw1, bw, tlw0, tlw1, blw);
    k_front<<<FRONT_BLKS, 256>>>(feats, bsize, inds, ts,
                                 mw0, mw1, mw2, lw0, lw1, lw2,
                                 tb0, tb1, bb, tlb0, tlb1, blb, out);
    k_pointmlp<<<Bb * PP, 128>>>(xyz, mb0, mb1, mb2);
    k_label<<<Bb * PP, 256>>>(blabel, lb0, lb1, lb2, out);
}

// round 13
// speedup vs baseline: 1.0408x; 1.0408x over previous
#include <cuda_runtime.h>
#include <math.h>

#define Bb 8
#define NPTS 20000
#define PP 256
#define SS 32
#define CC 256
#define NCLS 18

#define OFF_NF   6144
#define OFF_LAB  268288
#define OFF_INDS 792576

// ---- scratch ----
__device__ float d_featT[(size_t)Bb*NPTS*CC];   // [B][N][C]
__device__ float d_x[Bb*NPTS], d_y[Bb*NPTS], d_z[Bb*NPTS];
__device__ int   d_samp[Bb*PP*SS];
__device__ float d_center[Bb*PP*3];
__device__ float d_nf[Bb*PP*128];
__device__ float d_ss256[Bb*256];
__device__ float d_ss512[Bb*512];
// vectorized MLP weights: [(c4*O+o)*4+j] = W[o][c4*4+j] (0-pad)
__device__ float d_w0v[65*128*4];
__device__ float d_w1v[32*128*4];
__device__ float d_w2v[32*128*4];
__device__ float d_l0v[37*256*4];
__device__ float d_l1v[64*256*4];
__device__ float d_l2v[64*256*4];
// transposed time-MLP weights
__device__ float d_tw0T[128*512];
__device__ float d_tw1T[512*512];
__device__ float d_bwT[512*256];
__device__ float d_tlw0T[256*1024];
__device__ float d_tlw1T[1024*1024];
__device__ float d_blwT[1024*512];

// ---- packed f32x2 helpers ----
__device__ __forceinline__ unsigned long long pack2(float x, float y) {
    unsigned long long r;
    asm("mov.b64 %0, {%1, %2};" : "=l"(r) : "f"(x), "f"(y));
    return r;
}
__device__ __forceinline__ void unpack2(unsigned long long v, float& x, float& y) {
    asm("mov.b64 {%0, %1}, %2;" : "=f"(x), "=f"(y) : "l"(v));
}
__device__ __forceinline__ void ffma2(unsigned long long& d, unsigned long long a,
                                      unsigned long long b) {
    asm("fma.rn.f32x2 %0, %1, %2, %0;" : "+l"(d) : "l"(a), "l"(b));
}
__device__ __forceinline__ float gelu_exact(float x) {
    return 0.5f * x * (1.0f + erff(x * 0.70710678118654752f));
}
__device__ __forceinline__ float silu_f(float x) {
    return x / (1.0f + expf(-x));
}

// ============ launch 0: xyz SoA split ======================================
#define XYZ_BLKS ((Bb*NPTS + 255) / 256)          // 625
__global__ void __launch_bounds__(256)
k_prexyz(const float* __restrict__ xyz) {
    int i = blockIdx.x * 256 + threadIdx.x;
    if (i < Bb * NPTS) {
        d_x[i] = xyz[i * 3 + 0];
        d_y[i] = xyz[i * 3 + 1];
        d_z[i] = xyz[i * 3 + 2];
    }
}

// ============ launch 1: time-MLP weight transposes =========================
#define PREP2_TOTAL (128*512 + 512*512 + 512*256 + 256*1024 + 1024*1024 + 1024*512)
#define PREP2_BLKS (PREP2_TOTAL / 256)            // 9216
__device__ __forceinline__ void tr_one(float* dst, const float* src,
                                       int I, int O, int idx) {
    int o = idx % O, i = idx / O;
    dst[idx] = src[o * I + i];
}
__global__ void __launch_bounds__(256)
k_prep2(const float* __restrict__ tw0, const float* __restrict__ tw1,
        const float* __restrict__ bw, const float* __restrict__ tlw0,
        const float* __restrict__ tlw1, const float* __restrict__ blw) {
    int i = blockIdx.x * 256 + threadIdx.x;
    int off = 0;
    if (i < off + 128*512)   { tr_one(d_tw0T,  tw0,  128,  512,  i - off); return; } off += 128*512;
    if (i < off + 512*512)   { tr_one(d_tw1T,  tw1,  512,  512,  i - off); return; } off += 512*512;
    if (i < off + 512*256)   { tr_one(d_bwT,   bw,   512,  256,  i - off); return; } off += 512*256;
    if (i < off + 256*1024)  { tr_one(d_tlw0T, tlw0, 256,  1024, i - off); return; } off += 256*1024;
    if (i < off + 1024*1024) { tr_one(d_tlw1T, tlw1, 1024, 1024, i - off); return; } off += 1024*1024;
    if (i < off + 1024*512)  { tr_one(d_blwT,  blw,  1024, 512,  i - off); return; }
}

// ============ launch 2: MLP weight vectorization ===========================
#define S_W0 (65*128*4)
#define S_W1 (32*128*4)
#define S_L0 (37*256*4)
#define S_L1 (64*256*4)
#define PREP1_TOTAL (S_W0 + 2*S_W1 + S_L0 + 2*S_L1)
#define PREP1_BLKS ((PREP1_TOTAL + 255) / 256)    // 918
__device__ __forceinline__ void vec_one(float* dst, const float* W,
                                        int O, int Cin, int i) {
    int j = i & 3, r = i >> 2;
    int o = r % O, c4 = r / O, c = c4 * 4 + j;
    dst[i] = (c < Cin) ? W[o * Cin + c] : 0.f;
}
__global__ void __launch_bounds__(256)
k_prep1(const float* __restrict__ mw0, const float* __restrict__ mw1,
        const float* __restrict__ mw2, const float* __restrict__ lw0,
        const float* __restrict__ lw1, const float* __restrict__ lw2) {
    int i = blockIdx.x * 256 + threadIdx.x;
    int off = 0;
    if (i < off + S_W0) { vec_one(d_w0v, mw0, 128, 259, i - off); return; } off += S_W0;
    if (i < off + S_W1) { vec_one(d_w1v, mw1, 128, 128, i - off); return; } off += S_W1;
    if (i < off + S_W1) { vec_one(d_w2v, mw2, 128, 128, i - off); return; } off += S_W1;
    if (i < off + S_L0) { vec_one(d_l0v, lw0, 256, 146, i - off); return; } off += S_L0;
    if (i < off + S_L1) { vec_one(d_l1v, lw1, 256, 256, i - off); return; } off += S_L1;
    if (i < off + S_L1) { vec_one(d_l2v, lw2, 256, 256, i - off); return; }
}

// ============ launch 3: features transpose [B][C][N] -> [B][N][C] ==========
__global__ void k_featT(const float* __restrict__ feat) {
    __shared__ float tile[32][33];
    int b = blockIdx.z;
    int n0 = blockIdx.x * 32, c0 = blockIdx.y * 32;
    int tx = threadIdx.x, ty = threadIdx.y;   // 32 x 8
    const float* src = feat + ((size_t)b * CC + c0) * NPTS + n0;
    #pragma unroll
    for (int j = 0; j < 32; j += 8) tile[ty + j][tx] = src[(size_t)(ty + j) * NPTS + tx];
    __syncthreads();
    float* dst = d_featT + ((size_t)b * NPTS + n0) * CC + c0;
    #pragma unroll
    for (int j = 0; j < 32; j += 8) dst[(size_t)(ty + j) * CC + tx] = tile[tx][ty + j];
}

// ============ launch 4: k_seltime (select blocks + time blocks) ============
#define SEL_BLKS (Bb * PP)
#define SEG 2500                        // NPTS / 8 warps (NOT a multiple of 32!)

__device__ void do_select(int bp, int t, const float* __restrict__ bsize,
                          const int* __restrict__ inds, float* __restrict__ out) {
    __shared__ int cand[8][SS];
    __shared__ int wcnt[8];
    int b = bp >> 8;
    int lane = t & 31, wid = t >> 5;
    int ind = inds[bp];
    const float* xb = d_x + b * NPTS;
    const float* yb = d_y + b * NPTS;
    const float* zb = d_z + b * NPTS;
    float cx = xb[ind], cy = yb[ind], cz = zb[ind];
    float hx = bsize[bp * 3 + 0] * 0.5f;
    float hy = bsize[bp * 3 + 1] * 0.5f;
    float hz = bsize[bp * 3 + 2] * 0.5f;

    // each warp scans its own contiguous segment; SEG % 32 != 0 so the final
    // iteration's tail lanes MUST be masked out (i < segend) or they double-
    // count into the next warp's territory (the R9 bug).
    int segbeg = wid * SEG, segend = segbeg + SEG;
    int found = 0;
    for (int i0 = segbeg; i0 < segend && found < SS; i0 += 32) {
        int i = i0 + lane;
        bool in = (i < segend) &&
                  (fabsf(xb[i] - cx) <= hx) && (fabsf(yb[i] - cy) <= hy) &&
                  (fabsf(zb[i] - cz) <= hz);
        unsigned m = __ballot_sync(0xffffffffu, in);
        if (in) {
            int r = found + __popc(m & ((1u << lane) - 1u));
            if (r < SS) cand[wid][r] = i;
        }
        found += __popc(m);
    }
    if (lane == 0) wcnt[wid] = found < SS ? found : SS;
    __syncthreads();
    // merge: capped prefix is exact for ranks < 32 and for the cycling count
    if (t < SS) {
        int total = 0;
        #pragma unroll
        for (int w = 0; w < 8; w++) total += wcnt[w];
        int ce = total < SS ? total : SS;   // >= 1 (center is in its own box)
        int r = t % ce;
        int w = 0, acc = 0;
        while (w < 7 && r >= acc + wcnt[w]) { acc += wcnt[w]; w++; }
        d_samp[bp * SS + t] = cand[w][r - acc];
    }
    if (t < 3) {
        float cv = (t == 0) ? cx : ((t == 1) ? cy : cz);
        out[bp * 3 + t] = cv;
        d_center[bp * 3 + t] = cv;
    }
    if (t == 0) out[OFF_INDS + bp] = (float)ind;
}

__device__ void do_time(int blk, int t, const float* __restrict__ ts,
                        const float* __restrict__ tb0, const float* __restrict__ tb1,
                        const float* __restrict__ bb,
                        const float* __restrict__ tlb0, const float* __restrict__ tlb1,
                        const float* __restrict__ blb) {
    __shared__ float e[256];
    __shared__ float h1[1024];
    __shared__ float h2[1024];
    int chain = blk >> 3;
    int b = blk & 7;
    float tsv = ts[b];
    if (chain == 0) {
        if (t < 128) {
            int k = (t < 64) ? t : t - 64;
            float fr = expf((float)k * (float)(-9.210340371976184 / 63.0));
            float ev = tsv * fr;
            e[t] = (float)((t < 64) ? sin((double)ev) : cos((double)ev));
        }
        __syncthreads();
        #pragma unroll
        for (int k = 0; k < 2; k++) {
            int o = t + k * 256;
            float acc = tb0[o];
            #pragma unroll 4
            for (int i = 0; i < 128; i++) acc = fmaf(e[i], d_tw0T[i * 512 + o], acc);
            h1[o] = gelu_exact(acc);
        }
        __syncthreads();
        #pragma unroll
        for (int k = 0; k < 2; k++) {
            int o = t + k * 256;
            float acc = tb1[o];
            #pragma unroll 4
            for (int i = 0; i < 512; i++) acc = fmaf(h1[i], d_tw1T[i * 512 + o], acc);
            h2[o] = silu_f(acc);
        }
        __syncthreads();
        {
            float acc = bb[t];
            #pragma unroll 4
            for (int i = 0; i < 512; i++) acc = fmaf(h2[i], d_bwT[i * 256 + t], acc);
            d_ss256[b * 256 + t] = acc;
        }
    } else {
        if (t < 256) {
            int k = (t < 128) ? t : t - 128;
            float fr = expf((float)k * (float)(-9.210340371976184 / 127.0));
            float ev = tsv * fr;
            e[t] = (float)((t < 128) ? sin((double)ev) : cos((double)ev));
        }
        __syncthreads();
        #pragma unroll
        for (int k = 0; k < 4; k++) {
            int o = t + k * 256;
            float acc = tlb0[o];
            #pragma unroll 4
            for (int i = 0; i < 256; i++) acc = fmaf(e[i], d_tlw0T[i * 1024 + o], acc);
            h1[o] = gelu_exact(acc);
        }
        __syncthreads();
        #pragma unroll
        for (int k = 0; k < 4; k++) {
            int o = t + k * 256;
            float acc = tlb1[o];
            #pragma unroll 4
            for (int i = 0; i < 1024; i++) acc = fmaf(h1[i], d_tlw1T[i * 1024 + o], acc);
            h2[o] = silu_f(acc);
        }
        __syncthreads();
        #pragma unroll
        for (int k = 0; k < 2; k++) {
            int o = t + k * 256;
            float acc = blb[o];
            #pragma unroll 4
            for (int i = 0; i < 1024; i++) acc = fmaf(h2[i], d_blwT[i * 512 + o], acc);
            d_ss512[b * 512 + o] = acc;
        }
    }
}

__global__ void __launch_bounds__(256)
k_seltime(const float* __restrict__ bsize, const int* __restrict__ inds,
          const float* __restrict__ ts,
          const float* __restrict__ tb0, const float* __restrict__ tb1,
          const float* __restrict__ bb,
          const float* __restrict__ tlb0, const float* __restrict__ tlb1,
          const float* __restrict__ blb, float* __restrict__ out) {
    int blk = blockIdx.x;
    int t = threadIdx.x;
    if (blk < SEL_BLKS) { do_select(blk, t, bsize, inds, out); return; }
    do_time(blk - SEL_BLKS, t, ts, tb0, tb1, bb, tlb0, tlb1, blb);
}

// ============ launch 5: point MLP (64 thr, 2 outputs/thread, f32x2) ========
#define GROWS 260
#define RS 18            // row stride in float2
__global__ void __launch_bounds__(64)
k_pointmlp(const float* __restrict__ xyz,
           const float* __restrict__ mb0, const float* __restrict__ mb1,
           const float* __restrict__ mb2) {
    int bp = blockIdx.x;
    int b = bp >> 8;
    int t = threadIdx.x;
    __shared__ __align__(16) float2 g2[GROWS * RS];
    __shared__ int sidx[SS];
    __shared__ float ctr[3];
    float* gf = (float*)g2;
    if (t < SS) sidx[t] = d_samp[bp * SS + t];
    if (t < 3)  ctr[t] = d_center[bp * 3 + t];
    __syncthreads();
    if (t < SS) {
        const float* pt = xyz + ((size_t)b * NPTS + sidx[t]) * 3;
        #pragma unroll
        for (int d = 0; d < 3; d++) gf[d * (2 * RS) + t] = pt[d] - ctr[d];
        gf[259 * (2 * RS) + t] = 0.f;
    }
    {   // coalesced gather: 2 threads per sample, 32 float4 each
        int s = t >> 1, q = t & 1;
        const float4* fr = (const float4*)(d_featT + ((size_t)b * NPTS + sidx[s]) * CC);
        #pragma unroll
        for (int k = 0; k < 32; k++) {
            float4 v = fr[q + 2 * k];
            int c = 4 * (q + 2 * k);
            gf[(3 + c) * (2 * RS) + s] = v.x;
            gf[(4 + c) * (2 * RS) + s] = v.y;
            gf[(5 + c) * (2 * RS) + s] = v.z;
            gf[(6 + c) * (2 * RS) + s] = v.w;
        }
    }
    __syncthreads();

    unsigned long long accA[16], accB[16];
    // layer 0: 259(+pad) -> 128, outputs t and t+64
    {
        float bvA = mb0[t], bvB = mb0[t + 64];
        unsigned long long b2A = pack2(bvA, bvA), b2B = pack2(bvB, bvB);
        #pragma unroll
        for (int i = 0; i < 16; i++) { accA[i] = b2A; accB[i] = b2B; }
        const float4* wv = (const float4*)d_w0v;
        for (int c4 = 0; c4 < 65; c4++) {
            float4 wA = wv[c4 * 128 + t];
            float4 wB = wv[c4 * 128 + t + 64];
            #pragma unroll
            for (int cj = 0; cj < 4; cj++) {
                float wa = (cj == 0) ? wA.x : (cj == 1) ? wA.y : (cj == 2) ? wA.z : wA.w;
                float wb = (cj == 0) ? wB.x : (cj == 1) ? wB.y : (cj == 2) ? wB.z : wB.w;
                unsigned long long wpA = pack2(wa, wa), wpB = pack2(wb, wb);
                const ulonglong2* row = (const ulonglong2*)(g2 + (c4 * 4 + cj) * RS);
                #pragma unroll
                for (int s4 = 0; s4 < 8; s4++) {
                    ulonglong2 gg = row[s4];
                    ffma2(accA[2 * s4],     gg.x, wpA);
                    ffma2(accA[2 * s4 + 1], gg.y, wpA);
                    ffma2(accB[2 * s4],     gg.x, wpB);
                    ffma2(accB[2 * s4 + 1], gg.y, wpB);
                }
            }
        }
    }
    __syncthreads();
    float2* h0 = g2;
    float2* h1 = g2 + 128 * RS;
    #pragma unroll
    for (int i = 0; i < 16; i++) {
        float lo, hi;
        unpack2(accA[i], lo, hi);
        h0[t * RS + i] = make_float2(fmaxf(lo, 0.f), fmaxf(hi, 0.f));
        unpack2(accB[i], lo, hi);
        h0[(t + 64) * RS + i] = make_float2(fmaxf(lo, 0.f), fmaxf(hi, 0.f));
    }
    __syncthreads();
    for (int layer = 0; layer < 2; layer++) {
        const float4* wv = (const float4*)(layer == 0 ? d_w1v : d_w2v);
        float bvA = (layer == 0) ? mb1[t] : mb2[t];
        float bvB = (layer == 0) ? mb1[t + 64] : mb2[t + 64];
        const float2* hin = (layer == 0) ? h0 : h1;
        unsigned long long b2A = pack2(bvA, bvA), b2B = pack2(bvB, bvB);
        #pragma unroll
        for (int i = 0; i < 16; i++) { accA[i] = b2A; accB[i] = b2B; }
        for (int c4 = 0; c4 < 32; c4++) {
            float4 wA = wv[c4 * 128 + t];
            float4 wB = wv[c4 * 128 + t + 64];
            #pragma unroll
            for (int cj = 0; cj < 4; cj++) {
                float wa = (cj == 0) ? wA.x : (cj == 1) ? wA.y : (cj == 2) ? wA.z : wA.w;
                float wb = (cj == 0) ? wB.x : (cj == 1) ? wB.y : (cj == 2) ? wB.z : wB.w;
                unsigned long long wpA = pack2(wa, wa), wpB = pack2(wb, wb);
                const ulonglong2* row = (const ulonglong2*)(hin + (c4 * 4 + cj) * RS);
                #pragma unroll
                for (int s4 = 0; s4 < 8; s4++) {
                    ulonglong2 gg = row[s4];
                    ffma2(accA[2 * s4],     gg.x, wpA);
                    ffma2(accA[2 * s4 + 1], gg.y, wpA);
                    ffma2(accB[2 * s4],     gg.x, wpB);
                    ffma2(accB[2 * s4 + 1], gg.y, wpB);
                }
            }
        }
        __syncthreads();
        if (layer == 0) {
            #pragma unroll
            for (int i = 0; i < 16; i++) {
                float lo, hi;
                unpack2(accA[i], lo, hi);
                h1[t * RS + i] = make_float2(fmaxf(lo, 0.f), fmaxf(hi, 0.f));
                unpack2(accB[i], lo, hi);
                h1[(t + 64) * RS + i] = make_float2(fmaxf(lo, 0.f), fmaxf(hi, 0.f));
            }
            __syncthreads();
        } else {
            float mA = -1e30f, mB = -1e30f;
            #pragma unroll
            for (int i = 0; i < 16; i++) {
                float lo, hi;
                unpack2(accA[i], lo, hi);
                mA = fmaxf(mA, fmaxf(lo, hi));
                unpack2(accB[i], lo, hi);
                mB = fmaxf(mB, fmaxf(lo, hi));
            }
            d_nf[bp * 128 + t] = fmaxf(mA, 0.f);
            d_nf[bp * 128 + t + 64] = fmaxf(mB, 0.f);
        }
    }
}

// ============ launch 6: label branch (4 proposals/block) + FiLM ============
__global__ void __launch_bounds__(256)
k_label(const float* __restrict__ blabel,
        const float* __restrict__ lb0, const float* __restrict__ lb1,
        const float* __restrict__ lb2, float* __restrict__ out) {
    int bp0 = blockIdx.x * 4;
    int b = bp0 >> 8, p0 = bp0 & 255;
    int t = threadIdx.x;
    __shared__ __align__(16) float li[4][152];
    __shared__ __align__(16) float h[4][256];
    #pragma unroll
    for (int pp = 0; pp < 4; pp++) {
        if (t < 148) {
            float v = 0.f;
            if (t < NCLS) v = blabel[(bp0 + pp) * NCLS + t];
            else if (t < NCLS + 128) v = d_nf[(bp0 + pp) * 128 + (t - NCLS)];
            li[pp][t] = v;
        }
        if (t < 128) {   // new_features FiLM (torch repeat/chunk scrambling)
            int p = p0 + pp;
            float m = d_nf[(bp0 + pp) * 128 + t];
            int pm = p & 127;
            float sc = d_ss256[b * 256 + pm] + 1.f;
            float sh = d_ss256[b * 256 + 128 + pm];
            out[OFF_NF + ((size_t)b * 128 + t) * 256 + p] = fmaf(m, sc, sh);
        }
    }
    __syncthreads();
    float acc[4];
    // layer 0: 146 -> 256
    {
        float bv = lb0[t];
        #pragma unroll
        for (int pp = 0; pp < 4; pp++) acc[pp] = bv;
        const float4* wv = (const float4*)d_l0v;
        for (int c4 = 0; c4 < 37; c4++) {
            float4 w = wv[c4 * 256 + t];
            #pragma unroll
            for (int pp = 0; pp < 4; pp++) {
                float4 gv = *(const float4*)(&li[pp][c4 * 4]);
                acc[pp] = fmaf(gv.x, w.x, acc[pp]); acc[pp] = fmaf(gv.y, w.y, acc[pp]);
                acc[pp] = fmaf(gv.z, w.z, acc[pp]); acc[pp] = fmaf(gv.w, w.w, acc[pp]);
            }
        }
        #pragma unroll
        for (int pp = 0; pp < 4; pp++) h[pp][t] = fmaxf(acc[pp], 0.f);
    }
    __syncthreads();
    // layers 1,2: 256 -> 256
    for (int layer = 0; layer < 2; layer++) {
        const float4* wv = (const float4*)(layer == 0 ? d_l1v : d_l2v);
        float bv = (layer == 0) ? lb1[t] : lb2[t];
        #pragma unroll
        for (int pp = 0; pp < 4; pp++) acc[pp] = bv;
        for (int c4 = 0; c4 < 64; c4++) {
            float4 w = wv[c4 * 256 + t];
            #pragma unroll
            for (int pp = 0; pp < 4; pp++) {
                float4 gv = *(const float4*)(&h[pp][c4 * 4]);
                acc[pp] = fmaf(gv.x, w.x, acc[pp]); acc[pp] = fmaf(gv.y, w.y, acc[pp]);
                acc[pp] = fmaf(gv.z, w.z, acc[pp]); acc[pp] = fmaf(gv.w, w.w, acc[pp]);
            }
        }
        __syncthreads();
        if (layer == 0) {
            #pragma unroll
            for (int pp = 0; pp < 4; pp++) h[pp][t] = fmaxf(acc[pp], 0.f);
            __syncthreads();
        } else {
            #pragma unroll
            for (int pp = 0; pp < 4; pp++) {
                int p = p0 + pp;
                float val = fmaxf(acc[pp], 0.f);
                float sc = d_ss512[b * 512 + p] + 1.f;
                float sh = d_ss512[b * 512 + 256 + p];
                out[OFF_LAB + ((size_t)b * 256 + t) * 256 + p] = fmaf(val, sc, sh);
            }
        }
    }
}

extern "C" void kernel_launch(void* const* d_in, const int* in_sizes, int n_in,
                              void* d_out, int out_size) {
    const float* xyz    = (const float*)d_in[0];
    const float* feats  = (const float*)d_in[1];
    const float* bsize  = (const float*)d_in[2];
    const float* blabel = (const float*)d_in[3];
    const float* ts     = (const float*)d_in[4];
    const int*   inds   = (const int*)d_in[5];
    const float* mw0 = (const float*)d_in[6];  const float* mb0 = (const float*)d_in[7];
    const float* mw1 = (const float*)d_in[8];  const float* mb1 = (const float*)d_in[9];
    const float* mw2 = (const float*)d_in[10]; const float* mb2 = (const float*)d_in[11];
    const float* lw0 = (const float*)d_in[12]; const float* lb0 = (const float*)d_in[13];
    const float* lw1 = (const float*)d_in[14]; const float* lb1 = (const float*)d_in[15];
    const float* lw2 = (const float*)d_in[16]; const float* lb2 = (const float*)d_in[17];
    const float* tw0 = (const float*)d_in[18]; const float* tb0 = (const float*)d_in[19];
    const float* tw1 = (const float*)d_in[20]; const float* tb1 = (const float*)d_in[21];
    const float* bw  = (const float*)d_in[22]; const float* bb  = (const float*)d_in[23];
    const float* tlw0 = (const float*)d_in[24]; const float* tlb0 = (const float*)d_in[25];
    const float* tlw1 = (const float*)d_in[26]; const float* tlb1 = (const float*)d_in[27];
    const float* blw  = (const float*)d_in[28]; const float* blb  = (const float*)d_in[29];
    float* out = (float*)d_out;

    k_prexyz<<<XYZ_BLKS, 256>>>(xyz);                                         // 0
    k_prep2<<<PREP2_BLKS, 256>>>(tw0, tw1, bw, tlw0, tlw1, blw);              // 1
    k_prep1<<<PREP1_BLKS, 256>>>(mw0, mw1, mw2, lw0, lw1, lw2);               // 2
    k_featT<<<dim3(NPTS / 32, CC / 32, Bb), dim3(32, 8)>>>(feats);            // 3
    k_seltime<<<SEL_BLKS + 16, 256>>>(bsize, inds, ts, tb0, tb1, bb,
                                      tlb0, tlb1, blb, out);                  // 4
    k_pointmlp<<<Bb * PP, 64>>>(xyz, mb0, mb1, mb2);                          // 5 (ncu)
    k_label<<<Bb * PP / 4, 256>>>(blabel, lb0, lb1, lb2, out);                // 6
}